// round 5
// baseline (speedup 1.0000x reference)
#include <cuda_runtime.h>
#include <cstdint>

// Problem geometry (fixed: GRID = (32,32,32), 6 channels)
#define NCELL 32768          // 32*32*32
#define NCH   6
#define NCTA  128            // <= 148 SMs -> all CTAs co-resident, grid barrier safe
#define NTHR  256            // 128*256 = 32768 = one thread per cell
#define FLAG_STRIDE 64       // 64 u32 = 256B between flags -> distinct L2 slices

// Persistent device state (allocation-free scratch). Everything the barrier
// relies on is re-zeroed at the top of each launch, under the init barrier,
// so the kernel is deterministic across calls / graph replays.
__device__ __align__(16) float g_phi[2][NCH * NCELL];    // double-buffered phi
__device__ float    g_probe[8];                          // nxt values at target cell
__device__ unsigned g_flags[NCTA * FLAG_STRIDE];         // per-CTA arrival tokens
__device__ unsigned g_gen;                               // packed (token<<1)|reached
// init-barrier state (classic atomic barrier; gen is relative so it is
// self-consistent across replays without reset)
__device__ unsigned g_ib_arrive;
__device__ volatile unsigned g_ib_gen;

__device__ __forceinline__ void st_release_gpu_u32(unsigned* p, unsigned v) {
    asm volatile("st.release.gpu.global.u32 [%0], %1;" :: "l"(p), "r"(v) : "memory");
}
__device__ __forceinline__ unsigned ld_acquire_gpu_u32(const unsigned* p) {
    unsigned v;
    asm volatile("ld.acquire.gpu.global.u32 %0, [%1];" : "=r"(v) : "l"(p) : "memory");
    return v;
}

// Classic atomic grid barrier — used ONCE per launch (publishes init state,
// including the zeroed flags/gen/probe, grid-wide).
__device__ __forceinline__ void init_grid_sync()
{
    __syncthreads();
    if (threadIdx.x == 0) {
        __threadfence();
        unsigned gen = g_ib_gen;
        unsigned old = atomicAdd(&g_ib_arrive, 1u);
        if (old == NCTA - 1) {
            atomicExch(&g_ib_arrive, 0u);
            __threadfence();
            g_ib_gen = gen + 1u;
        } else {
            while (g_ib_gen == gen) { }
        }
        __threadfence();   // acquire: IVALL -> fresh view of init state
    }
    __syncthreads();
}

__global__ void __launch_bounds__(NTHR, 1)
flash_wave_kernel(const float* __restrict__ D,
                  const int* __restrict__ p_sx, const int* __restrict__ p_sy,
                  const int* __restrict__ p_sz, const int* __restrict__ p_ex,
                  const int* __restrict__ p_ey, const int* __restrict__ p_ez,
                  const int* __restrict__ p_mi,
                  float* __restrict__ out)
{
    __shared__ int s_par[7];
    __shared__ int s_reached;

    const int c = blockIdx.x * NTHR + threadIdx.x;   // this thread's cell

    if (threadIdx.x == 0) {
        s_par[0] = *p_sx; s_par[1] = *p_sy; s_par[2] = *p_sz;
        s_par[3] = *p_ex; s_par[4] = *p_ey; s_par[5] = *p_ez;
        s_par[6] = *p_mi;
        g_flags[blockIdx.x * FLAG_STRIDE] = 0;       // reset my arrival flag
    }
    if (c == 0) {
        g_gen = 0;
        #pragma unroll
        for (int o = 0; o < NCH; o++) g_probe[o] = 0.0f;
    }
    __syncthreads();

    const int srcc  = (s_par[0] << 10) + (s_par[1] << 5) + s_par[2];
    const int ct    = (s_par[3] << 10) + (s_par[4] << 5) + s_par[5];
    const int maxit = s_par[6];

    const int x = c >> 10;
    const int y = (c >> 5) & 31;
    const int z = c & 31;

    // Register-resident active_D for this cell: D[o][i][cell] + 0.95 (36 regs).
    float Dr[36];
    #pragma unroll
    for (int k = 0; k < 36; k++) Dr[k] = D[k * NCELL + c] + 0.95f;

    // phi0: zeros except all 6 channels = 1 at the source cell.
    const float v0 = (c == srcc) ? 1.0f : 0.0f;
    #pragma unroll
    for (int i = 0; i < NCH; i++) g_phi[0][i * NCELL + c] = v0;

    init_grid_sync();   // publish phi0 + zeroed barrier state grid-wide

    // Current phi values for my cell live in registers; loaded from the nxt
    // buffer at the END of each step (via .cg so no stale-L1 hazard).
    float v[6];
    #pragma unroll
    for (int i = 0; i < 6; i++) v[i] = v0;

    int p = 0;   // current phi buffer index
    int t = 0;   // next history slab to write

    for (;;) {
        // history[t] = phi (pre-update) — streaming stores, keep L2 for phi/D.
        {
            float* hout = out + (size_t)t * (NCH * NCELL);
            #pragma unroll
            for (int i = 0; i < 6; i++) __stcs(&hout[i * NCELL + c], v[i]);
        }

        t++;
        if (t >= maxit) break;   // final slab written; last update is discarded

        // phi_out[o] = clip(sum_i Dr[o][i] * v[i], 0, 1)
        float r[6];
        #pragma unroll
        for (int o = 0; o < 6; o++) {
            float a = Dr[o * 6] * v[0];
            #pragma unroll
            for (int i = 1; i < 6; i++) a = fmaf(Dr[o * 6 + i], v[i], a);
            r[o] = fminf(fmaxf(a, 0.0f), 1.0f);
        }

        // Scatter into nxt = g_phi[p^1]; every location written exactly once.
        // Writes landing on the target cell mirror into g_probe.
        {
            float* __restrict__ nxt = g_phi[p ^ 1];
            if (x < 31) { int d = c + 1024; nxt[0 * NCELL + d] = r[0]; if (d == ct) g_probe[0] = r[0]; }
            else        { nxt[1 * NCELL + c] = 0.0f; }
            if (x > 0)  { int d = c - 1024; nxt[1 * NCELL + d] = r[1]; if (d == ct) g_probe[1] = r[1]; }
            else        { nxt[0 * NCELL + c] = 0.0f; }
            if (y < 31) { int d = c + 32;   nxt[2 * NCELL + d] = r[2]; if (d == ct) g_probe[2] = r[2]; }
            else        { nxt[3 * NCELL + c] = 0.0f; }
            if (y > 0)  { int d = c - 32;   nxt[3 * NCELL + d] = r[3]; if (d == ct) g_probe[3] = r[3]; }
            else        { nxt[2 * NCELL + c] = 0.0f; }
            if (z < 31) { int d = c + 1;    nxt[4 * NCELL + d] = r[4]; if (d == ct) g_probe[4] = r[4]; }
            else        { nxt[5 * NCELL + c] = 0.0f; }
            if (z > 0)  { int d = c - 1;    nxt[5 * NCELL + d] = r[5]; if (d == ct) g_probe[5] = r[5]; }
            else        { nxt[4 * NCELL + c] = 0.0f; }
        }

        // ---- Distributed-flag grid barrier, token = t ----
        // Arrival: one release store per CTA to its own 256B-strided flag
        // (parallel across L2 slices — no same-address atomic serialization).
        // Combine: CTA0 warp0 polls all flags with acquire loads, then
        // release-publishes (token<<1)|reached in a single word.
        __syncthreads();
        if (blockIdx.x == 0) {
            if (threadIdx.x < 32) {
                const unsigned tok = (unsigned)t;
                for (int b = 1 + threadIdx.x; b < NCTA; b += 32) {
                    while (ld_acquire_gpu_u32(&g_flags[b * FLAG_STRIDE]) < tok) { }
                }
                __syncwarp();
                if (threadIdx.x == 0) {
                    __threadfence();   // IVALL -> fresh probe reads
                    float s = g_probe[0] + g_probe[1] + g_probe[2]
                            + g_probe[3] + g_probe[4] + g_probe[5];
                    unsigned packed = (tok << 1) | (s > 0.01f ? 1u : 0u);
                    st_release_gpu_u32(&g_gen, packed);
                    s_reached = (int)(packed & 1u);
                }
            }
            __syncthreads();
        } else {
            if (threadIdx.x == 0) {
                st_release_gpu_u32(&g_flags[blockIdx.x * FLAG_STRIDE], (unsigned)t);
                unsigned g;
                do { g = ld_acquire_gpu_u32(&g_gen); } while ((g >> 1) != (unsigned)t);
                s_reached = (int)(g & 1u);
            }
            __syncthreads();
        }

        if (s_reached) { p ^= 1; break; }   // g_phi[p] is now the frozen phi

        // Load next v from the buffer just written, bypassing L1 (no staleness).
        {
            const float* __restrict__ np = g_phi[p ^ 1];
            #pragma unroll
            for (int i = 0; i < 6; i++) v[i] = __ldcg(&np[i * NCELL + c]);
        }
        p ^= 1;
    }

    // Tail: history[t..maxit-1] all equal the frozen phi. Bulk streaming fill.
    if (t < maxit) {
        const float4* __restrict__ src4 = reinterpret_cast<const float4*>(g_phi[p]);
        float4* __restrict__ out4       = reinterpret_cast<float4*>(out);
        const int NV4 = NCH * NCELL / 4;   // 49152
        for (int idx = c; idx < NV4; idx += NCTA * NTHR) {
            float4 val = __ldcg(&src4[idx]);   // L2 read, never stale
            for (int u = t; u < maxit; u++) {
                __stcs(&out4[(size_t)u * NV4 + idx], val);
            }
        }
    }
}

extern "C" void kernel_launch(void* const* d_in, const int* in_sizes, int n_in,
                              void* d_out, int out_size)
{
    const float* D  = (const float*)d_in[0];
    const int*   sx = (const int*)d_in[1];
    const int*   sy = (const int*)d_in[2];
    const int*   sz = (const int*)d_in[3];
    const int*   ex = (const int*)d_in[4];
    const int*   ey = (const int*)d_in[5];
    const int*   ez = (const int*)d_in[6];
    const int*   mi = (const int*)d_in[7];

    flash_wave_kernel<<<NCTA, NTHR>>>(D, sx, sy, sz, ex, ey, ez, mi, (float*)d_out);
}

// round 6
// speedup vs baseline: 1.8665x; 1.8665x over previous
#include <cuda_runtime.h>
#include <cstdint>

// Problem geometry (fixed: GRID = (32,32,32), 6 channels)
#define NCELL 32768          // 32*32*32
#define NCH   6
#define NCTA  128            // <= 148 SMs -> all CTAs co-resident, grid barrier safe
#define NTHR  256            // 128*256 = 32768 = one thread per cell
#define NGEN  16             // replicated release words (8 spinners each)
#define GEN_STRIDE 32        // 32 u32 = 128B between release words
#define NV4   (NCH * NCELL / 4)   // 49152 float4 per history slab

// Persistent device state (allocation-free scratch). All barrier state is
// re-zeroed at the top of each launch, published by the init barrier, so the
// kernel is deterministic across calls / graph replays.
__device__ __align__(16) float g_phi[2][NCH * NCELL];    // double-buffered phi
__device__ float    g_probe[8];                          // nxt values at target cell
__device__ unsigned g_arrive;                            // monotonic arrival counter
__device__ volatile unsigned g_gen[NGEN * GEN_STRIDE];   // replicated release tokens
__device__ int      g_tail_start;                        // first frozen slab index
__device__ int      g_tail_buf;                          // which phi buffer is frozen
__device__ int      g_maxit;                             // max_iterations
// init-barrier state (classic atomic barrier; gen is relative so it is
// self-consistent across replays without reset)
__device__ unsigned g_ib_arrive;
__device__ volatile unsigned g_ib_gen;

// Classic atomic grid barrier — used ONCE per launch (publishes init state,
// including the zeroed counter/gen/probe, grid-wide).
__device__ __forceinline__ void init_grid_sync()
{
    __syncthreads();
    if (threadIdx.x == 0) {
        __threadfence();
        unsigned gen = g_ib_gen;
        unsigned old = atomicAdd(&g_ib_arrive, 1u);
        if (old == NCTA - 1) {
            atomicExch(&g_ib_arrive, 0u);
            __threadfence();
            g_ib_gen = gen + 1u;
        } else {
            while (g_ib_gen == gen) { }
        }
        __threadfence();   // acquire: fresh view of init state
    }
    __syncthreads();
}

__global__ void __launch_bounds__(NTHR, 1)
flash_wave_kernel(const float* __restrict__ D,
                  const int* __restrict__ p_sx, const int* __restrict__ p_sy,
                  const int* __restrict__ p_sz, const int* __restrict__ p_ex,
                  const int* __restrict__ p_ey, const int* __restrict__ p_ez,
                  const int* __restrict__ p_mi,
                  float* __restrict__ out)
{
    __shared__ int s_par[7];
    __shared__ int s_reached;

    const int c = blockIdx.x * NTHR + threadIdx.x;   // this thread's cell

    if (threadIdx.x == 0) {
        s_par[0] = *p_sx; s_par[1] = *p_sy; s_par[2] = *p_sz;
        s_par[3] = *p_ex; s_par[4] = *p_ey; s_par[5] = *p_ez;
        s_par[6] = *p_mi;
    }
    if (c == 0) {
        g_arrive = 0;
        #pragma unroll
        for (int i = 0; i < NGEN; i++) g_gen[i * GEN_STRIDE] = 0u;
        #pragma unroll
        for (int o = 0; o < NCH; o++) g_probe[o] = 0.0f;
    }
    __syncthreads();

    const int srcc  = (s_par[0] << 10) + (s_par[1] << 5) + s_par[2];
    const int ct    = (s_par[3] << 10) + (s_par[4] << 5) + s_par[5];
    const int maxit = s_par[6];

    const int x = c >> 10;
    const int y = (c >> 5) & 31;
    const int z = c & 31;

    // Register-resident active_D for this cell: D[o][i][cell] + 0.95 (36 regs).
    float Dr[36];
    #pragma unroll
    for (int k = 0; k < 36; k++) Dr[k] = D[k * NCELL + c] + 0.95f;

    // phi0: zeros except all 6 channels = 1 at the source cell.
    const float v0 = (c == srcc) ? 1.0f : 0.0f;
    #pragma unroll
    for (int i = 0; i < NCH; i++) g_phi[0][i * NCELL + c] = v0;

    init_grid_sync();   // publish phi0 + zeroed barrier state grid-wide

    // Current phi values for my cell live in registers; re-loaded from the
    // freshly-written buffer at the end of each step via __ldcg (L2-only, so
    // no stale-L1 hazard and no acquire fence needed).
    float v[6];
    #pragma unroll
    for (int i = 0; i < 6; i++) v[i] = v0;

    int p = 0;   // current phi buffer index
    int t = 0;   // next history slab to write

    for (;;) {
        // history[t] = phi (pre-update) — streaming stores, keep L2 for phi/D.
        {
            float* hout = out + (size_t)t * (NCH * NCELL);
            #pragma unroll
            for (int i = 0; i < 6; i++) __stcs(&hout[i * NCELL + c], v[i]);
        }

        t++;
        if (t >= maxit) break;   // final slab written; last update is discarded

        // phi_out[o] = clip(sum_i Dr[o][i] * v[i], 0, 1)
        float r[6];
        #pragma unroll
        for (int o = 0; o < 6; o++) {
            float a = Dr[o * 6] * v[0];
            #pragma unroll
            for (int i = 1; i < 6; i++) a = fmaf(Dr[o * 6 + i], v[i], a);
            r[o] = fminf(fmaxf(a, 0.0f), 1.0f);
        }

        // Scatter into nxt = g_phi[p^1]; every location written exactly once.
        // Writes landing on the target cell mirror into g_probe.
        {
            float* __restrict__ nxt = g_phi[p ^ 1];
            if (x < 31) { int d = c + 1024; nxt[0 * NCELL + d] = r[0]; if (d == ct) g_probe[0] = r[0]; }
            else        { nxt[1 * NCELL + c] = 0.0f; }
            if (x > 0)  { int d = c - 1024; nxt[1 * NCELL + d] = r[1]; if (d == ct) g_probe[1] = r[1]; }
            else        { nxt[0 * NCELL + c] = 0.0f; }
            if (y < 31) { int d = c + 32;   nxt[2 * NCELL + d] = r[2]; if (d == ct) g_probe[2] = r[2]; }
            else        { nxt[3 * NCELL + c] = 0.0f; }
            if (y > 0)  { int d = c - 32;   nxt[3 * NCELL + d] = r[3]; if (d == ct) g_probe[3] = r[3]; }
            else        { nxt[2 * NCELL + c] = 0.0f; }
            if (z < 31) { int d = c + 1;    nxt[4 * NCELL + d] = r[4]; if (d == ct) g_probe[4] = r[4]; }
            else        { nxt[5 * NCELL + c] = 0.0f; }
            if (z > 0)  { int d = c - 1;    nxt[5 * NCELL + d] = r[5]; if (d == ct) g_probe[5] = r[5]; }
            else        { nxt[4 * NCELL + c] = 0.0f; }
        }

        // ---- Grid barrier (monotonic counter + replicated release words) ----
        // Arrivals: pipelined same-address atomicAdd (fast at L2).
        // Last arriver reads the probes (control-dependent on the atomic's
        // result, so ordered after all arrivals) and fans the packed token
        // (t<<1)|reached out to 16 words 128B apart; each word has only 8
        // spinning CTA leaders -> no same-address load-contention pileup.
        __syncthreads();
        if (threadIdx.x == 0) {
            __threadfence();   // release this CTA's phi/probe/history writes
            unsigned packed;
            unsigned old = atomicAdd(&g_arrive, 1u);
            if (old == (unsigned)(NCTA * t - 1)) {
                float s = __ldcg(&g_probe[0]) + __ldcg(&g_probe[1])
                        + __ldcg(&g_probe[2]) + __ldcg(&g_probe[3])
                        + __ldcg(&g_probe[4]) + __ldcg(&g_probe[5]);
                packed = ((unsigned)t << 1) | (s > 0.01f ? 1u : 0u);
                #pragma unroll
                for (int i = 0; i < NGEN; i++) g_gen[i * GEN_STRIDE] = packed;
            } else {
                volatile unsigned* w = &g_gen[(blockIdx.x >> 3) * GEN_STRIDE];
                do { packed = *w; } while ((packed >> 1) != (unsigned)t);
            }
            s_reached = (int)(packed & 1u);
        }
        __syncthreads();

        if (s_reached) { p ^= 1; break; }   // g_phi[p] is now the frozen phi

        // Load next v from the buffer just written (L2-only, never stale).
        {
            const float* __restrict__ np = g_phi[p ^ 1];
            #pragma unroll
            for (int i = 0; i < 6; i++) v[i] = __ldcg(&np[i * NCELL + c]);
        }
        p ^= 1;
    }

    // Publish tail parameters for the fill kernel (visible at kernel boundary).
    if (c == 0) {
        g_tail_start = t;
        g_tail_buf   = p;
        g_maxit      = maxit;
    }
}

// Tail fill: history[t0..maxit-1] all equal the frozen phi. Full-chip grid so
// the 160+ MB of writes stream at DRAM rate instead of being issue-limited by
// 128 CTAs. gridDim = (8, 384): slab = blockIdx.y, 8 CTAs x 256 thr per slab.
__global__ void __launch_bounds__(256)
tail_fill_kernel(float* __restrict__ out)
{
    const int t0 = g_tail_start;
    const int mi = g_maxit;
    const int u  = blockIdx.y;
    if (u < t0 || u >= mi) return;

    const float4* __restrict__ src4 =
        reinterpret_cast<const float4*>(g_phi[g_tail_buf]);
    float4* __restrict__ dst4 =
        reinterpret_cast<float4*>(out + (size_t)u * (NCH * NCELL));

    const int stride = gridDim.x * blockDim.x;   // 8*256 = 2048
    for (int idx = blockIdx.x * blockDim.x + threadIdx.x; idx < NV4; idx += stride) {
        __stcs(&dst4[idx], __ldcg(&src4[idx]));
    }
}

extern "C" void kernel_launch(void* const* d_in, const int* in_sizes, int n_in,
                              void* d_out, int out_size)
{
    const float* D  = (const float*)d_in[0];
    const int*   sx = (const int*)d_in[1];
    const int*   sy = (const int*)d_in[2];
    const int*   sz = (const int*)d_in[3];
    const int*   ex = (const int*)d_in[4];
    const int*   ey = (const int*)d_in[5];
    const int*   ez = (const int*)d_in[6];
    const int*   mi = (const int*)d_in[7];

    flash_wave_kernel<<<NCTA, NTHR>>>(D, sx, sy, sz, ex, ey, ez, mi, (float*)d_out);
    tail_fill_kernel<<<dim3(8, 384), 256>>>((float*)d_out);
}

// round 7
// speedup vs baseline: 2.8019x; 1.5012x over previous
#include <cuda_runtime.h>
#include <cstdint>

// Problem geometry (fixed: GRID = (32,32,32), 6 channels)
#define NCELL 32768
#define NCH   6
#define NCTA  128            // all CTAs co-resident -> grid barrier safe
#define NTHR  256            // 128*256 = 32768 = one thread per cell
#define NGEN  16             // replicated release words (8 spinners each)
#define GEN_STRIDE 32        // 128B apart -> distinct L2 slices
#define NV4   (NCH * NCELL / 4)

// Persistent device scratch (allocation-free). Barrier state is re-zeroed at
// the top of each launch and published by the init barrier -> deterministic
// across calls / graph replays.
__device__ __align__(16) float g_po[2][NCH * NCELL];     // double-buffered po = clip(D·phi)
__device__ __align__(16) float g_frozen[NCH * NCELL];    // frozen phi for tail fill
__device__ float    g_probe[2];                          // target sums at t+1, t+2
__device__ unsigned g_arrive;                            // monotonic arrival counter
__device__ volatile unsigned g_gen[NGEN * GEN_STRIDE];   // replicated release tokens
__device__ int      g_tail_start;
__device__ int      g_maxit;
// init-barrier state (classic; gen relative -> replay-safe without reset)
__device__ unsigned g_ib_arrive;
__device__ volatile unsigned g_ib_gen;

__device__ __forceinline__ float clip01(float a) {
    return fminf(fmaxf(a, 0.0f), 1.0f);
}

__device__ __forceinline__ void init_grid_sync()
{
    __syncthreads();
    if (threadIdx.x == 0) {
        __threadfence();
        unsigned gen = g_ib_gen;
        unsigned old = atomicAdd(&g_ib_arrive, 1u);
        if (old == NCTA - 1) {
            atomicExch(&g_ib_arrive, 0u);
            __threadfence();
            g_ib_gen = gen + 1u;
        } else {
            while (g_ib_gen == gen) { }
        }
        __threadfence();
    }
    __syncthreads();
}

__global__ void __launch_bounds__(NTHR, 1)
flash_wave_kernel(const float* __restrict__ D,
                  const int* __restrict__ p_sx, const int* __restrict__ p_sy,
                  const int* __restrict__ p_sz, const int* __restrict__ p_ex,
                  const int* __restrict__ p_ey, const int* __restrict__ p_ez,
                  const int* __restrict__ p_mi,
                  float* __restrict__ out)
{
    __shared__ int s_par[7];
    __shared__ int s_flags;

    const int c = blockIdx.x * NTHR + threadIdx.x;

    if (threadIdx.x == 0) {
        s_par[0] = *p_sx; s_par[1] = *p_sy; s_par[2] = *p_sz;
        s_par[3] = *p_ex; s_par[4] = *p_ey; s_par[5] = *p_ez;
        s_par[6] = *p_mi;
    }
    __syncthreads();

    const int srcc  = (s_par[0] << 10) + (s_par[1] << 5) + s_par[2];
    const int ct    = (s_par[3] << 10) + (s_par[4] << 5) + s_par[5];
    const int maxit = s_par[6];

    if (c == 0) {
        g_arrive = 0;
        #pragma unroll
        for (int i = 0; i < NGEN; i++) g_gen[i * GEN_STRIDE] = 0u;
        g_probe[0] = 0.0f; g_probe[1] = 0.0f;
        g_maxit = maxit;
        g_tail_start = maxit;   // default: no tail (overwritten on frozen exit)
    }

    const int x = c >> 10;
    const int y = (c >> 5) & 31;
    const int z = c & 31;

    // Direction tables: channel ch's SOURCE offset (gather form).
    // nxt[0,x]=po[0,x-1]; nxt[1,x]=po[1,x+1]; nxt[2,y]=po[2,y-1];
    // nxt[3,y]=po[3,y+1]; nxt[4,z]=po[4,z-1]; nxt[5,z]=po[5,z+1].
    const int dx[6] = {-1, 1, 0, 0, 0, 0};
    const int dy[6] = { 0, 0,-1, 1, 0, 0};
    const int dz[6] = { 0, 0, 0, 0,-1, 1};

    // Own active_D rows (36 regs): D[o][i][c] + 0.95
    float Dr[36];
    #pragma unroll
    for (int k = 0; k < 36; k++) Dr[k] = D[k * NCELL + c] + 0.95f;

    // Level-1 gather: validity mask + clamped address per channel.
    float m1[6];
    int   a1[6];
    #pragma unroll
    for (int ch = 0; ch < 6; ch++) {
        int x1 = x + dx[ch], y1 = y + dy[ch], z1 = z + dz[ch];
        bool ok = ((unsigned)x1 < 32u) & ((unsigned)y1 < 32u) & ((unsigned)z1 < 32u);
        m1[ch] = ok ? 1.0f : 0.0f;
        a1[ch] = ok ? ((x1 << 10) | (y1 << 5) | z1) : c;
    }

    // Neighbor-D rows with ALL boundary conditions folded in as zeros, and
    // level-2 gather addresses (clamped-safe). Dn[ch][i] = D[ch][i](s_ch)+0.95
    // if (s_ch in grid) && (s_ch's source-i in grid), else 0.
    float Dn[36];
    int   a2[36];
    #pragma unroll
    for (int ch = 0; ch < 6; ch++) {
        int x1 = x + dx[ch], y1 = y + dy[ch], z1 = z + dz[ch];
        bool ok1 = ((unsigned)x1 < 32u) & ((unsigned)y1 < 32u) & ((unsigned)z1 < 32u);
        int s1i = ok1 ? ((x1 << 10) | (y1 << 5) | z1) : c;
        #pragma unroll
        for (int i = 0; i < 6; i++) {
            int x2 = x1 + dx[i], y2 = y1 + dy[i], z2 = z1 + dz[i];
            bool ok2 = ok1 & ((unsigned)x2 < 32u) & ((unsigned)y2 < 32u) & ((unsigned)z2 < 32u);
            a2[ch * 6 + i] = ok2 ? ((x2 << 10) | (y2 << 5) | z2) : c;
            Dn[ch * 6 + i] = ok2 ? (D[(ch * 6 + i) * NCELL + s1i] + 0.95f) : 0.0f;
        }
    }

    // Init: phi0 = zeros except all 6 channels = 1 at source cell.
    const float v0 = (c == srcc) ? 1.0f : 0.0f;
    {
        // history[0] = phi0
        #pragma unroll
        for (int i = 0; i < 6; i++) __stcs(&out[i * NCELL + c], v0);
    }

    // po(0) at own cell = clip(Dr · phi0), kept in regs + stored to g_po[0].
    float po_reg[6];
    #pragma unroll
    for (int o = 0; o < 6; o++) {
        float a = Dr[o * 6] * v0;
        #pragma unroll
        for (int i = 1; i < 6; i++) a = fmaf(Dr[o * 6 + i], v0, a);
        po_reg[o] = clip01(a);
    }
    #pragma unroll
    for (int o = 0; o < 6; o++) g_po[0][o * NCELL + c] = po_reg[o];

    init_grid_sync();   // publish po(0) + zeroed barrier state grid-wide

    int t = 0;   // phi(t) is the last committed state; history[0..t] written
    int p = 0;   // g_po[p] holds po(t)
    int k = 1;   // superstep / barrier token

    for (;;) {
        if (t + 1 >= maxit) break;                       // history complete

        const float* __restrict__ po_rd = g_po[p];

        // ---- v1 = phi(t+1): one gather per channel ----
        float v1[6];
        #pragma unroll
        for (int ch = 0; ch < 6; ch++)
            v1[ch] = m1[ch] * __ldcg(&po_rd[ch * NCELL + a1[ch]]);

        // history[t+1] = v1 (always correct; freeze affects t+2 onward)
        {
            float* h1 = out + (size_t)(t + 1) * (NCH * NCELL);
            #pragma unroll
            for (int ch = 0; ch < 6; ch++) __stcs(&h1[ch * NCELL + c], v1[ch]);
        }
        if (t + 1 == maxit - 1) break;                   // done, no tail

        // ---- v2 = phi(t+2): recompute neighbors' po(t+1) from po(t) ----
        // v2[ch] = clip( sum_i Dn[ch][i] * po(t)[i](s_ch + off_i) );
        // the i == ch^1 term lands back on c -> use register po_reg.
        float v2[6];
        #pragma unroll
        for (int ch = 0; ch < 6; ch++) {
            float a = 0.0f;
            #pragma unroll
            for (int i = 0; i < 6; i++) {
                float g = (i == (ch ^ 1)) ? po_reg[i]
                        : __ldcg(&po_rd[i * NCELL + a2[ch * 6 + i]]);
                if (i == 0) a = Dn[ch * 6] * g;
                else        a = fmaf(Dn[ch * 6 + i], g, a);
            }
            v2[ch] = clip01(a);
        }

        // po(t+2) at own cell, stored to the other buffer (pre-barrier).
        float po2[6];
        #pragma unroll
        for (int o = 0; o < 6; o++) {
            float a = Dr[o * 6] * v2[0];
            #pragma unroll
            for (int i = 1; i < 6; i++) a = fmaf(Dr[o * 6 + i], v2[i], a);
            po2[o] = clip01(a);
        }
        {
            float* __restrict__ po_wr = g_po[p ^ 1];
            #pragma unroll
            for (int o = 0; o < 6; o++) po_wr[o * NCELL + c] = po2[o];
        }

        // Target owner publishes probe sums for steps t+1 and t+2.
        if (c == ct) {
            g_probe[0] = v1[0] + v1[1] + v1[2] + v1[3] + v1[4] + v1[5];
            g_probe[1] = v2[0] + v2[1] + v2[2] + v2[3] + v2[4] + v2[5];
        }

        // ---- Grid barrier k: monotonic counter + replicated release words.
        // Last arriver reads probes and packs (k<<2)|(r1<<1)|r2 into token.
        __syncthreads();
        if (threadIdx.x == 0) {
            __threadfence();
            unsigned packed;
            unsigned old = atomicAdd(&g_arrive, 1u);
            if (old == (unsigned)(NCTA * k - 1)) {
                float s1 = __ldcg(&g_probe[0]);
                float s2 = __ldcg(&g_probe[1]);
                packed = ((unsigned)k << 2)
                       | (s1 > 0.01f ? 2u : 0u)
                       | (s2 > 0.01f ? 1u : 0u);
                #pragma unroll
                for (int i = 0; i < NGEN; i++) g_gen[i * GEN_STRIDE] = packed;
            } else {
                volatile unsigned* w = &g_gen[(blockIdx.x >> 3) * GEN_STRIDE];
                do { packed = *w; } while ((packed >> 2) != (unsigned)k);
            }
            s_flags = (int)(packed & 3u);
        }
        __syncthreads();
        const int fl = s_flags;

        if (fl & 2) {
            // Reached at t+1: frozen phi = v1. history[t+1] already written;
            // slabs [t+2, maxit) = v1 via tail kernel.
            #pragma unroll
            for (int ch = 0; ch < 6; ch++) g_frozen[ch * NCELL + c] = v1[ch];
            if (c == 0) g_tail_start = t + 2;
            break;
        }

        // history[t+2] = v2
        {
            float* h2 = out + (size_t)(t + 2) * (NCH * NCELL);
            #pragma unroll
            for (int ch = 0; ch < 6; ch++) __stcs(&h2[ch * NCELL + c], v2[ch]);
        }

        if (fl & 1) {
            // Reached at t+2: frozen phi = v2; slabs [t+3, maxit) = v2.
            #pragma unroll
            for (int ch = 0; ch < 6; ch++) g_frozen[ch * NCELL + c] = v2[ch];
            if (c == 0) g_tail_start = t + 3;
            break;
        }

        #pragma unroll
        for (int o = 0; o < 6; o++) po_reg[o] = po2[o];
        p ^= 1;
        t += 2;
        k += 1;
    }
}

// Tail fill: slabs [g_tail_start, g_maxit) all equal g_frozen. Full-chip grid
// streams the writes at DRAM rate. gridDim = (8, 384): slab = blockIdx.y.
__global__ void __launch_bounds__(256)
tail_fill_kernel(float* __restrict__ out)
{
    const int t0 = g_tail_start;
    const int mi = g_maxit;
    const int u  = blockIdx.y;
    if (u < t0 || u >= mi) return;

    const float4* __restrict__ src4 = reinterpret_cast<const float4*>(g_frozen);
    float4* __restrict__ dst4 =
        reinterpret_cast<float4*>(out + (size_t)u * (NCH * NCELL));

    const int stride = gridDim.x * blockDim.x;   // 2048
    for (int idx = blockIdx.x * blockDim.x + threadIdx.x; idx < NV4; idx += stride) {
        __stcs(&dst4[idx], __ldcg(&src4[idx]));
    }
}

extern "C" void kernel_launch(void* const* d_in, const int* in_sizes, int n_in,
                              void* d_out, int out_size)
{
    const float* D  = (const float*)d_in[0];
    const int*   sx = (const int*)d_in[1];
    const int*   sy = (const int*)d_in[2];
    const int*   sz = (const int*)d_in[3];
    const int*   ex = (const int*)d_in[4];
    const int*   ey = (const int*)d_in[5];
    const int*   ez = (const int*)d_in[6];
    const int*   mi = (const int*)d_in[7];

    flash_wave_kernel<<<NCTA, NTHR>>>(D, sx, sy, sz, ex, ey, ez, mi, (float*)d_out);
    tail_fill_kernel<<<dim3(8, 384), 256>>>((float*)d_out);
}

// round 9
// speedup vs baseline: 3.3610x; 1.1995x over previous
#include <cuda_runtime.h>
#include <cstdint>

// Problem geometry (fixed: GRID = (32,32,32), 6 channels)
#define NCELL 32768
#define NCH   6
#define NCTA  128            // all CTAs co-resident
#define NTHR  256            // one thread per cell
#define FLAG_STRIDE 64       // 256B apart -> distinct L2 slices
#define NV4   (NCH * NCELL / 4)
// Freeze-token ring: one write-once slot per superstep, 8 replicas each.
#define NSLOT 160            // >= ceil(300/2)+2 supersteps
#define NREP  8              // 16 CTAs poll each replica
#define TOK_STRIDE 32        // 128B apart

// Persistent device scratch (allocation-free). All sync state re-zeroed at the
// top of each launch, published by the one-time init barrier -> deterministic
// across calls / graph replays.
__device__ __align__(16) float g_po[2][NCH * NCELL];     // double-buffered po = clip(D·phi)
__device__ __align__(16) float g_frozen[NCH * NCELL];    // frozen phi for tail fill
__device__ volatile unsigned g_flags[NCTA * FLAG_STRIDE];// per-CTA superstep counters
__device__ volatile unsigned g_tok[NSLOT * NREP * TOK_STRIDE]; // write-once tokens
__device__ int      g_tail_start;
__device__ int      g_maxit;
// init-barrier state (classic; gen relative -> replay-safe without reset)
__device__ unsigned g_ib_arrive;
__device__ volatile unsigned g_ib_gen;

__device__ __forceinline__ float clip01(float a) {
    return fminf(fmaxf(a, 0.0f), 1.0f);
}

// Classic atomic grid barrier — used ONCE per launch to publish init state.
__device__ __forceinline__ void init_grid_sync()
{
    __syncthreads();
    if (threadIdx.x == 0) {
        __threadfence();
        unsigned gen = g_ib_gen;
        unsigned old = atomicAdd(&g_ib_arrive, 1u);
        if (old == NCTA - 1) {
            atomicExch(&g_ib_arrive, 0u);
            __threadfence();
            g_ib_gen = gen + 1u;
        } else {
            while (g_ib_gen == gen) { }
        }
        __threadfence();
    }
    __syncthreads();
}

__global__ void __launch_bounds__(NTHR, 1)
flash_wave_kernel(const float* __restrict__ D,
                  const int* __restrict__ p_sx, const int* __restrict__ p_sy,
                  const int* __restrict__ p_sz, const int* __restrict__ p_ex,
                  const int* __restrict__ p_ey, const int* __restrict__ p_ez,
                  const int* __restrict__ p_mi,
                  float* __restrict__ out)
{
    __shared__ int   s_par[7];
    __shared__ int   s_flags;
    __shared__ int   s_nb[12];      // neighbor CTA ids (halo distance <= 2)
    __shared__ int   s_nnb;
    __shared__ float s_probe[2];    // target-cell sums (target CTA only)

    const int bid = blockIdx.x;
    const int c   = bid * NTHR + threadIdx.x;   // this thread's cell

    if (threadIdx.x == 0) {
        s_par[0] = *p_sx; s_par[1] = *p_sy; s_par[2] = *p_sz;
        s_par[3] = *p_ex; s_par[4] = *p_ey; s_par[5] = *p_ez;
        s_par[6] = *p_mi;
        g_flags[bid * FLAG_STRIDE] = 0u;        // reset my superstep counter

        // Neighbor CTA set: CTA covers x = bid>>2 (one x-plane quarter? no:
        // 1024 cells per x-plane, 256 per CTA -> CTA = (X = bid>>2, Y = bid&3,
        // 8 y-values, full z). Distance-2 halo touches:
        // (X±2,Y), (X±1,Y+{-1,0,1}), (X,Y±1).
        const int X = bid >> 2, Y = bid & 3;
        const int off[10][2] = {{-2,0},{2,0},{-1,-1},{-1,0},{-1,1},
                                { 1,-1},{1,0},{ 1, 1},{ 0,-1},{0,1}};
        int n = 0;
        for (int i = 0; i < 10; i++) {
            int Xn = X + off[i][0], Yn = Y + off[i][1];
            if ((unsigned)Xn < 32u && (unsigned)Yn < 4u)
                s_nb[n++] = Xn * 4 + Yn;
        }
        s_nnb = n;
    }
    // Zero all token slots (write-once per launch; 1280 words).
    if (c < NSLOT * NREP) g_tok[c * TOK_STRIDE] = 0u;
    __syncthreads();

    const int srcc  = (s_par[0] << 10) + (s_par[1] << 5) + s_par[2];
    const int ct    = (s_par[3] << 10) + (s_par[4] << 5) + s_par[5];
    const int maxit = s_par[6];
    const int tgt_cta = ct >> 8;                // CTA owning the target cell

    if (c == 0) {
        g_maxit = maxit;
        g_tail_start = maxit;   // default: no tail
    }

    const int x = c >> 10;
    const int y = (c >> 5) & 31;
    const int z = c & 31;

    // Channel ch's SOURCE offset (gather form).
    const int dx[6] = {-1, 1, 0, 0, 0, 0};
    const int dy[6] = { 0, 0,-1, 1, 0, 0};
    const int dz[6] = { 0, 0, 0, 0,-1, 1};

    // Own active_D rows (36 regs): D[o][i][c] + 0.95
    float Dr[36];
    #pragma unroll
    for (int k = 0; k < 36; k++) Dr[k] = D[k * NCELL + c] + 0.95f;

    // Level-1 gather: validity mask + clamped address per channel.
    float m1[6];
    int   a1[6];
    #pragma unroll
    for (int ch = 0; ch < 6; ch++) {
        int x1 = x + dx[ch], y1 = y + dy[ch], z1 = z + dz[ch];
        bool ok = ((unsigned)x1 < 32u) & ((unsigned)y1 < 32u) & ((unsigned)z1 < 32u);
        m1[ch] = ok ? 1.0f : 0.0f;
        a1[ch] = ok ? ((x1 << 10) | (y1 << 5) | z1) : c;
    }

    // Neighbor-D rows with all boundary conditions folded in as zeros, and
    // level-2 gather addresses. Dn[ch][i] = D[ch][i](s_ch)+0.95 if valid, else 0.
    float Dn[36];
    int   a2[36];
    #pragma unroll
    for (int ch = 0; ch < 6; ch++) {
        int x1 = x + dx[ch], y1 = y + dy[ch], z1 = z + dz[ch];
        bool ok1 = ((unsigned)x1 < 32u) & ((unsigned)y1 < 32u) & ((unsigned)z1 < 32u);
        int s1i = ok1 ? ((x1 << 10) | (y1 << 5) | z1) : c;
        #pragma unroll
        for (int i = 0; i < 6; i++) {
            int x2 = x1 + dx[i], y2 = y1 + dy[i], z2 = z1 + dz[i];
            bool ok2 = ok1 & ((unsigned)x2 < 32u) & ((unsigned)y2 < 32u) & ((unsigned)z2 < 32u);
            a2[ch * 6 + i] = ok2 ? ((x2 << 10) | (y2 << 5) | z2) : c;
            Dn[ch * 6 + i] = ok2 ? (D[(ch * 6 + i) * NCELL + s1i] + 0.95f) : 0.0f;
        }
    }

    // Init: phi0 = zeros except all 6 channels = 1 at source; history[0] = phi0.
    const float v0 = (c == srcc) ? 1.0f : 0.0f;
    #pragma unroll
    for (int i = 0; i < 6; i++) __stcs(&out[i * NCELL + c], v0);

    // po(0) at own cell, kept in regs + stored to g_po[0].
    float po_reg[6];
    #pragma unroll
    for (int o = 0; o < 6; o++) {
        float a = Dr[o * 6] * v0;
        #pragma unroll
        for (int i = 1; i < 6; i++) a = fmaf(Dr[o * 6 + i], v0, a);
        po_reg[o] = clip01(a);
    }
    #pragma unroll
    for (int o = 0; o < 6; o++) g_po[0][o * NCELL + c] = po_reg[o];

    init_grid_sync();   // publish po(0) + zeroed flags/tokens grid-wide

    int t = 0;   // phi(t) = last committed state; history[0..t] written
    int p = 0;   // g_po[p] holds po(t)
    int k = 1;   // superstep counter (flag value / token slot)

    for (;;) {
        if (t + 1 >= maxit) break;

        const float* __restrict__ po_rd = g_po[p];

        // ---- v1 = phi(t+1): one gather per channel (L2, never stale) ----
        float v1[6];
        #pragma unroll
        for (int ch = 0; ch < 6; ch++)
            v1[ch] = m1[ch] * __ldcg(&po_rd[ch * NCELL + a1[ch]]);

        if (t + 1 == maxit - 1) {
            // Last slab: write history[t+1] and finish (no tail).
            float* h1 = out + (size_t)(t + 1) * (NCH * NCELL);
            #pragma unroll
            for (int ch = 0; ch < 6; ch++) __stcs(&h1[ch * NCELL + c], v1[ch]);
            break;
        }

        // ---- v2 = phi(t+2): recompute neighbors' po(t+1) from po(t) ----
        float v2[6];
        #pragma unroll
        for (int ch = 0; ch < 6; ch++) {
            float a = 0.0f;
            #pragma unroll
            for (int i = 0; i < 6; i++) {
                float g = (i == (ch ^ 1)) ? po_reg[i]
                        : __ldcg(&po_rd[i * NCELL + a2[ch * 6 + i]]);
                if (i == 0) a = Dn[ch * 6] * g;
                else        a = fmaf(Dn[ch * 6 + i], g, a);
            }
            v2[ch] = clip01(a);
        }

        // po(t+2) at own cell -> other buffer (before flag publish).
        float po2[6];
        #pragma unroll
        for (int o = 0; o < 6; o++) {
            float a = Dr[o * 6] * v2[0];
            #pragma unroll
            for (int i = 1; i < 6; i++) a = fmaf(Dr[o * 6 + i], v2[i], a);
            po2[o] = clip01(a);
        }
        {
            float* __restrict__ po_wr = g_po[p ^ 1];
            #pragma unroll
            for (int o = 0; o < 6; o++) po_wr[o * NCELL + c] = po2[o];
        }

        // Target thread publishes probe sums to ITS CTA's smem.
        if (c == ct) {
            s_probe[0] = v1[0] + v1[1] + v1[2] + v1[3] + v1[4] + v1[5];
            s_probe[1] = v2[0] + v2[1] + v2[2] + v2[3] + v2[4] + v2[5];
        }

        // ---- Publish: token slot k (target CTA only), then flag = k ----
        __syncthreads();   // all po2 stores + s_probe done
        if (threadIdx.x == 0) {
            __threadfence();                      // release po2 (gpu scope)
            if (bid == tgt_cta) {
                // Write-once token for THIS superstep: nonzero since k >= 1.
                unsigned pk = ((unsigned)k << 2)
                            | (s_probe[0] > 0.01f ? 2u : 0u)
                            | (s_probe[1] > 0.01f ? 1u : 0u);
                #pragma unroll
                for (int r = 0; r < NREP; r++)
                    g_tok[(k * NREP + r) * TOK_STRIDE] = pk;
            }
            g_flags[bid * FLAG_STRIDE] = (unsigned)k;
        }

        // history[t+1] = v1 — overlaps with the waits below.
        {
            float* h1 = out + (size_t)(t + 1) * (NCH * NCELL);
            #pragma unroll
            for (int ch = 0; ch < 6; ch++) __stcs(&h1[ch * NCELL + c], v1[ch]);
        }

        // ---- Wait: neighbors >= k (data + anti-dep for next superstep),
        //      and the EXACT superstep-k freeze token. Leader-warp lanes poll
        //      in parallel. Exact slot -> every CTA sees the same decision for
        //      superstep k -> uniform break -> no deadlock.
        if (threadIdx.x < 32) {
            const int nn = s_nnb;
            if ((int)threadIdx.x < nn) {
                volatile unsigned* w = &g_flags[s_nb[threadIdx.x] * FLAG_STRIDE];
                while (*w < (unsigned)k) { }
            } else if (threadIdx.x == 30) {
                volatile unsigned* w = &g_tok[(k * NREP + (bid & (NREP - 1))) * TOK_STRIDE];
                unsigned pk;
                do { pk = *w; } while (pk == 0u);
                s_flags = (int)(pk & 3u);
            }
            __syncwarp();
        }
        __syncthreads();
        const int fl = s_flags;

        if (fl & 2) {
            // Reached at t+1: frozen phi = v1; slabs [t+2, maxit) via tail.
            #pragma unroll
            for (int ch = 0; ch < 6; ch++) g_frozen[ch * NCELL + c] = v1[ch];
            if (c == 0) g_tail_start = t + 2;
            break;
        }

        // history[t+2] = v2
        {
            float* h2 = out + (size_t)(t + 2) * (NCH * NCELL);
            #pragma unroll
            for (int ch = 0; ch < 6; ch++) __stcs(&h2[ch * NCELL + c], v2[ch]);
        }

        if (fl & 1) {
            // Reached at t+2: frozen phi = v2; slabs [t+3, maxit) via tail.
            #pragma unroll
            for (int ch = 0; ch < 6; ch++) g_frozen[ch * NCELL + c] = v2[ch];
            if (c == 0) g_tail_start = t + 3;
            break;
        }

        #pragma unroll
        for (int o = 0; o < 6; o++) po_reg[o] = po2[o];
        p ^= 1;
        t += 2;
        k += 1;
    }
}

// Tail fill: slabs [g_tail_start, g_maxit) all equal g_frozen.
// One load, many stores: each thread owns one float4 of the slab, loads it
// once, streams it into a contiguous range of slabs (pure-write).
// Grid: x = 192 CTAs x 256 thr = 49152 threads (one per float4), y = 6 chunks.
__global__ void __launch_bounds__(256)
tail_fill_kernel(float* __restrict__ out)
{
    const int t0 = g_tail_start;
    const int mi = g_maxit;
    const int nslab = mi - t0;
    if (nslab <= 0) return;

    const int idx = blockIdx.x * blockDim.x + threadIdx.x;
    if (idx >= NV4) return;

    const float4 val = __ldcg(&reinterpret_cast<const float4*>(g_frozen)[idx]);
    float4* __restrict__ dst4 = reinterpret_cast<float4*>(out);

    const int per = (nslab + gridDim.y - 1) / gridDim.y;
    const int u0  = t0 + blockIdx.y * per;
    const int u1  = (u0 + per < mi) ? (u0 + per) : mi;
    for (int u = u0; u < u1; u++)
        __stcs(&dst4[(size_t)u * NV4 + idx], val);
}

extern "C" void kernel_launch(void* const* d_in, const int* in_sizes, int n_in,
                              void* d_out, int out_size)
{
    const float* D  = (const float*)d_in[0];
    const int*   sx = (const int*)d_in[1];
    const int*   sy = (const int*)d_in[2];
    const int*   sz = (const int*)d_in[3];
    const int*   ex = (const int*)d_in[4];
    const int*   ey = (const int*)d_in[5];
    const int*   ez = (const int*)d_in[6];
    const int*   mi = (const int*)d_in[7];

    flash_wave_kernel<<<NCTA, NTHR>>>(D, sx, sy, sz, ex, ey, ez, mi, (float*)d_out);
    tail_fill_kernel<<<dim3(192, 6), 256>>>((float*)d_out);
}